// round 1
// baseline (speedup 1.0000x reference)
#include <cuda_runtime.h>
#include <math.h>
#include <stdint.h>

#define NBINS 15

// ---------------- device-global scratch (allocation-free) ----------------
__device__ unsigned long long g_confq[NBINS];   // quantized conf sums (conf * 2^30)
__device__ unsigned int       g_cnt[NBINS];     // counts
__device__ unsigned int       g_acc[NBINS];     // accuracy counts
__device__ int                g_tgt64;          // 1 if target is int64, 0 if int32

// ---------------- kernel 0: zero accumulators + detect target dtype ------
__global__ void ece_zero_detect(const int* __restrict__ tgt_as_i32, int N) {
    int i = threadIdx.x;
    if (i < NBINS) { g_confq[i] = 0ull; g_cnt[i] = 0u; g_acc[i] = 0u; }
    if (i == 0) {
        // If the target buffer is int64 (little-endian, values in [0, C) >= 0),
        // every odd 32-bit word is zero. With int32 data these words are random
        // targets; P(first 128 odd words all zero) ~ (1/1000)^128 ~ 0.
        int n = N < 128 ? N : 128;
        int all_zero = 1;
        for (int k = 0; k < n; k++) {
            if (tgt_as_i32[2 * k + 1] != 0) { all_zero = 0; break; }
        }
        g_tgt64 = all_zero;
    }
}

// ---------------- kernel 1: per-row softmax-max + argmax + binning -------
// One warp per row. Each lane stages VPL float4 vectors in registers
// (front-batched LDG.128), pass1 = max/argmax, pass2 = sum of exp.
// Exactly one MUFU.EX2 per element -> stays HBM-bound.
template<int VPL>
__global__ __launch_bounds__(256)
void ece_main(const float* __restrict__ logits,
              const void*  __restrict__ target,
              int N, int C)
{
    const int NV   = C >> 2;                  // float4 per row
    const int lane = threadIdx.x & 31;
    const int warp = threadIdx.x >> 5;
    const int wpb  = blockDim.x >> 5;
    const int gwarp = blockIdx.x * wpb + warp;
    const int totalWarps = gridDim.x * wpb;

    __shared__ unsigned long long s_confq[NBINS];
    __shared__ unsigned int       s_cnt[NBINS];
    __shared__ unsigned int       s_acc[NBINS];
    if (threadIdx.x < NBINS) {
        s_confq[threadIdx.x] = 0ull; s_cnt[threadIdx.x] = 0u; s_acc[threadIdx.x] = 0u;
    }
    __syncthreads();

    const int is64 = g_tgt64;
    const long long* __restrict__ t64 = (const long long*)target;
    const int*       __restrict__ t32 = (const int*)target;

    for (int row = gwarp; row < N; row += totalWarps) {
        const float4* __restrict__ row4 =
            (const float4*)(logits + (size_t)row * (size_t)C);

        float4 buf[VPL];
        #pragma unroll
        for (int j = 0; j < VPL; j++) {
            int vi = lane + j * 32;
            if (vi < NV) buf[j] = __ldg(row4 + vi);
            else         buf[j] = make_float4(-INFINITY, -INFINITY, -INFINITY, -INFINITY);
        }

        // pass 1: lane-local max + first-occurrence argmax
        float m = -INFINITY; int idx = 0x7fffffff;
        #pragma unroll
        for (int j = 0; j < VPL; j++) {
            int base = 4 * (lane + j * 32);
            if (buf[j].x > m) { m = buf[j].x; idx = base;     }
            if (buf[j].y > m) { m = buf[j].y; idx = base + 1; }
            if (buf[j].z > m) { m = buf[j].z; idx = base + 2; }
            if (buf[j].w > m) { m = buf[j].w; idx = base + 3; }
        }
        float mm = (m == -INFINITY) ? 0.0f : m;   // safety for empty lanes

        // pass 2: sum of exp(l - m); padded -INF entries contribute exp(-inf)=0
        float s0 = 0.f, s1 = 0.f;
        #pragma unroll
        for (int j = 0; j < VPL; j++) {
            s0 += __expf(buf[j].x - mm);
            s1 += __expf(buf[j].y - mm);
            s0 += __expf(buf[j].z - mm);
            s1 += __expf(buf[j].w - mm);
        }
        float s = s0 + s1;

        // warp reduce (max, argmax, rescaled sum); lane 0 ends correct
        #pragma unroll
        for (int off = 16; off; off >>= 1) {
            float m2 = __shfl_down_sync(0xffffffffu, m,  off);
            float s2 = __shfl_down_sync(0xffffffffu, s,  off);
            int   i2 = __shfl_down_sync(0xffffffffu, idx, off);
            if (m2 > m) {
                s = s * __expf(m - m2) + s2; m = m2; idx = i2;
            } else if (m2 == m) {
                s += s2; if (i2 < idx) idx = i2;
            } else {
                s += s2 * __expf(m2 - m);
            }
        }

        if (lane == 0) {
            float conf = 1.0f / s;             // exp(m-m)/sum = max softmax prob
            int b = (int)ceilf(conf * (float)NBINS) - 1;
            b = min(max(b, 0), NBINS - 1);
            unsigned long long qc =
                (unsigned long long)__float2ull_rn(conf * 1073741824.0f); // *2^30
            atomicAdd(&s_confq[b], qc);
            atomicAdd(&s_cnt[b], 1u);
            long long tgt = is64 ? t64[row] : (long long)t32[row];
            if ((long long)idx == tgt) atomicAdd(&s_acc[b], 1u);
        }
    }

    __syncthreads();
    if (threadIdx.x < NBINS) {
        if (s_cnt[threadIdx.x]) {
            atomicAdd(&g_confq[threadIdx.x], s_confq[threadIdx.x]);
            atomicAdd(&g_cnt[threadIdx.x],   s_cnt[threadIdx.x]);
            atomicAdd(&g_acc[threadIdx.x],   s_acc[threadIdx.x]);
        }
    }
}

// ---------------- generic fallback (online softmax, scalar loads) --------
__global__ __launch_bounds__(256)
void ece_main_generic(const float* __restrict__ logits,
                      const void*  __restrict__ target,
                      int N, int C)
{
    const int lane = threadIdx.x & 31;
    const int warp = threadIdx.x >> 5;
    const int wpb  = blockDim.x >> 5;
    const int gwarp = blockIdx.x * wpb + warp;
    const int totalWarps = gridDim.x * wpb;

    __shared__ unsigned long long s_confq[NBINS];
    __shared__ unsigned int       s_cnt[NBINS];
    __shared__ unsigned int       s_acc[NBINS];
    if (threadIdx.x < NBINS) {
        s_confq[threadIdx.x] = 0ull; s_cnt[threadIdx.x] = 0u; s_acc[threadIdx.x] = 0u;
    }
    __syncthreads();

    const int is64 = g_tgt64;
    const long long* __restrict__ t64 = (const long long*)target;
    const int*       __restrict__ t32 = (const int*)target;

    for (int row = gwarp; row < N; row += totalWarps) {
        const float* __restrict__ r = logits + (size_t)row * (size_t)C;
        float m = -INFINITY, s = 0.f; int idx = 0x7fffffff;
        for (int c = lane; c < C; c += 32) {
            float v = __ldg(r + c);
            if (v > m) { s = s * __expf(m - v) + 1.0f; m = v; idx = c; }
            else       { s += __expf(v - m); }
        }
        #pragma unroll
        for (int off = 16; off; off >>= 1) {
            float m2 = __shfl_down_sync(0xffffffffu, m,  off);
            float s2 = __shfl_down_sync(0xffffffffu, s,  off);
            int   i2 = __shfl_down_sync(0xffffffffu, idx, off);
            if (m2 == -INFINITY) continue;
            if (m2 > m)       { s = s * __expf(m - m2) + s2; m = m2; idx = i2; }
            else if (m2 == m) { s += s2; if (i2 < idx) idx = i2; }
            else              { s += s2 * __expf(m2 - m); }
        }
        if (lane == 0) {
            float conf = 1.0f / s;
            int b = (int)ceilf(conf * (float)NBINS) - 1;
            b = min(max(b, 0), NBINS - 1);
            unsigned long long qc =
                (unsigned long long)__float2ull_rn(conf * 1073741824.0f);
            atomicAdd(&s_confq[b], qc);
            atomicAdd(&s_cnt[b], 1u);
            long long tgt = is64 ? t64[row] : (long long)t32[row];
            if ((long long)idx == tgt) atomicAdd(&s_acc[b], 1u);
        }
    }

    __syncthreads();
    if (threadIdx.x < NBINS) {
        if (s_cnt[threadIdx.x]) {
            atomicAdd(&g_confq[threadIdx.x], s_confq[threadIdx.x]);
            atomicAdd(&g_cnt[threadIdx.x],   s_cnt[threadIdx.x]);
            atomicAdd(&g_acc[threadIdx.x],   s_acc[threadIdx.x]);
        }
    }
}

// ---------------- kernel 2: finalize (ece, mean conf, mean acc) ----------
__global__ void ece_finalize(float* __restrict__ out, int out_size, int N)
{
    if (blockIdx.x == 0 && threadIdx.x == 0) {
        const double inv_q = 1.0 / 1073741824.0;
        double ece = 0.0, tot_conf = 0.0, tot_acc = 0.0;
        double invN = 1.0 / (double)N;
        for (int b = 0; b < NBINS; b++) {
            unsigned int cnt = g_cnt[b];
            double conf_sum = (double)g_confq[b] * inv_q;
            double acc_sum  = (double)g_acc[b];
            tot_conf += conf_sum;
            tot_acc  += acc_sum;
            if (cnt > 0) {
                double dc = (double)cnt;
                double avg_conf = conf_sum / dc;
                double avg_acc  = acc_sum / dc;
                double prop     = dc * invN;
                ece += (avg_conf - avg_acc) * prop;   // NO abs(), faithful to ref
            }
        }
        if (out_size > 0) out[0] = (float)ece;
        if (out_size > 1) out[1] = (float)(tot_conf * invN);
        if (out_size > 2) out[2] = (float)(tot_acc * invN);
        for (int i = 3; i < out_size; i++) out[i] = 0.0f;
    }
}

// ---------------- launch --------------------------------------------------
extern "C" void kernel_launch(void* const* d_in, const int* in_sizes, int n_in,
                              void* d_out, int out_size)
{
    const float* logits = (const float*)d_in[0];
    const void*  target = d_in[1];
    int N = in_sizes[1];
    int C = in_sizes[0] / N;

    ece_zero_detect<<<1, 32>>>((const int*)target, N);

    dim3 block(256);
    dim3 grid(1216);   // grid-stride; one warp per row

    int NV = C >> 2;
    if ((C & 3) == 0 && NV >= 32 && NV <= 256) {
        int vpl = (NV + 31) >> 5;
        switch (vpl) {
            case 1: ece_main<1><<<grid, block>>>(logits, target, N, C); break;
            case 2: ece_main<2><<<grid, block>>>(logits, target, N, C); break;
            case 3: ece_main<3><<<grid, block>>>(logits, target, N, C); break;
            case 4: ece_main<4><<<grid, block>>>(logits, target, N, C); break;
            case 5: ece_main<5><<<grid, block>>>(logits, target, N, C); break;
            case 6: ece_main<6><<<grid, block>>>(logits, target, N, C); break;
            case 7: ece_main<7><<<grid, block>>>(logits, target, N, C); break;
            default: ece_main<8><<<grid, block>>>(logits, target, N, C); break;
        }
    } else {
        ece_main_generic<<<grid, block>>>(logits, target, N, C);
    }

    ece_finalize<<<1, 32>>>((float*)d_out, out_size, N);
}